// round 1
// baseline (speedup 1.0000x reference)
#include <cuda_runtime.h>
#include <cstdint>

// Output: (BATCH=256, SEQ=512, DIM=64) fp32.
// inputs:   (256, 512) fp32 (token ids or numeric values)
// tables:   (3, 100000, 64) fp32
// table_ids:(512) int32, pattern [0,1,2,-1]
//
// One thread per float4 of output -> 16 threads per (b,s) row.

#define BATCH 256
#define SEQ   512
#define DIM   64
#define VOCAB 100000

__global__ void __launch_bounds__(256)
emb_gather_kernel(const float* __restrict__ inputs,
                  const float* __restrict__ tables,
                  const int*   __restrict__ table_ids,
                  float4*      __restrict__ out)
{
    int gidx = blockIdx.x * blockDim.x + threadIdx.x;   // [0, BATCH*SEQ*16)
    int row  = gidx >> 4;          // (b, s) flattened: b*SEQ + s
    int lane = gidx & 15;          // which float4 within the 64-float row
    int s    = row & (SEQ - 1);

    float v  = __ldg(&inputs[row]);
    int  tid = __ldg(&table_ids[s]);

    float4 r;
    if (tid >= 0) {
        // token id stored as float; exactly representable (< 2^24)
        long long idx = (long long)tid * VOCAB + (int)v;
        r = __ldg(((const float4*)tables) + idx * (DIM / 4) + lane);
    } else {
        r = make_float4(v, v, v, v);
    }
    out[gidx] = r;
}

extern "C" void kernel_launch(void* const* d_in, const int* in_sizes, int n_in,
                              void* d_out, int out_size)
{
    const float* inputs    = (const float*)d_in[0];
    const float* tables    = (const float*)d_in[1];
    const int*   table_ids = (const int*)d_in[2];
    float4*      out       = (float4*)d_out;

    int total_f4 = BATCH * SEQ * (DIM / 4);   // 2,097,152 threads
    int threads  = 256;
    int blocks   = total_f4 / threads;        // 8192
    emb_gather_kernel<<<blocks, threads>>>(inputs, tables, table_ids, out);
}